// round 1
// baseline (speedup 1.0000x reference)
#include <cuda_runtime.h>

// Problem constants
#define II 17
#define HH 128
#define TT 19
#define BBATCH 32768
#define GG 512            // 4*H gate width
#define ROWS 32           // batch rows per CTA
#define NTHR 512

typedef unsigned long long u64;

// Transposed W_hh: [k=0..127][n=0..511], 256 KB, L2-resident.
__device__ __align__(16) float g_WtHH[HH * GG];

__device__ __forceinline__ u64 fma2(u64 a, u64 b, u64 c) {
    u64 d;
    asm("fma.rn.f32x2 %0, %1, %2, %3;" : "=l"(d) : "l"(a), "l"(b), "l"(c));
    return d;
}
__device__ __forceinline__ u64 pack2(float v) {
    u64 d;
    asm("mov.b64 %0, {%1, %1};" : "=l"(d) : "f"(v));
    return d;
}
__device__ __forceinline__ void unpack2(u64 a, float& lo, float& hi) {
    asm("mov.b64 {%0, %1}, %2;" : "=f"(lo), "=f"(hi) : "l"(a));
}
__device__ __forceinline__ float sigf(float x) {
    return 1.0f / (1.0f + __expf(-x));
}
__device__ __forceinline__ float tanh_fast(float x) {
    // 2*sigmoid(2x) - 1 ; __expf rel err ~1e-6 -> plenty for 1e-3 threshold
    return 2.0f / (1.0f + __expf(-2.0f * x)) - 1.0f;
}

// One-time (idempotent) transpose of W_hh [512,128] -> g_WtHH [128,512]
__global__ void whh_transpose_kernel(const float* __restrict__ W_hh) {
    int idx = blockIdx.x * blockDim.x + threadIdx.x;
    if (idx < HH * GG) {
        int n = idx / HH;
        int k = idx % HH;
        g_WtHH[k * GG + n] = W_hh[idx];
    }
}

// SMEM float offsets
#define OFF_H     0        // h  [32][129]
#define OFF_C     4128     // c  [32][129]
#define OFF_WIH   8256     // Wih^T [17][512]
#define OFF_WOUT  16960    // Wout  [17][128]
#define OFF_BIAS  19136    // b_ih + b_hh [512]
#define OFF_BOUT  19648    // b_out [17] (padded)
#define OFF_XS    19680    // x tile [32][17]
#define OFF_YS    20224    // y tile [17][33]
#define SMEM_FLOATS 20800
#define SMEM_BYTES  (SMEM_FLOATS * 4)

__global__ void __launch_bounds__(NTHR)
flow_lstm_kernel(const float* __restrict__ x,
                 const float* __restrict__ W_ih,
                 const float* __restrict__ b_ih,
                 const float* __restrict__ b_hh,
                 const float* __restrict__ W_out,
                 const float* __restrict__ b_out,
                 float* __restrict__ out) {
    extern __shared__ float sm[];
    float* h_s    = sm + OFF_H;     // [32][129] (129 pad -> conflict-free both patterns)
    float* c_s    = sm + OFF_C;     // [32][129]
    float* wih_s  = sm + OFF_WIH;   // [ii][n]  transposed: [17][512]
    float* wout_s = sm + OFF_WOUT;  // [i][k]   [17][128]
    float* bias_s = sm + OFF_BIAS;  // [512]
    float* bout_s = sm + OFF_BOUT;  // [17]
    float* xs     = sm + OFF_XS;    // [32][17]
    float* ys     = sm + OFF_YS;    // [17][33]

    const int tid = threadIdx.x;
    const int tx  = tid & 31;       // hidden-unit group: hu = tx*4
    const int ty  = tid >> 5;       // 0..15 : rows m = ty*2 + {0,1}
    const int b0  = blockIdx.x * ROWS;
    const int hu  = tx * 4;

    // ---- one-time per-CTA setup ----
    for (int idx = tid; idx < GG * II; idx += NTHR) {
        int n = idx / II, i = idx % II;
        wih_s[i * GG + n] = W_ih[idx];              // transpose into smem
    }
    for (int idx = tid; idx < GG; idx += NTHR)
        bias_s[idx] = b_ih[idx] + b_hh[idx];
    for (int idx = tid; idx < II * HH; idx += NTHR)
        wout_s[idx] = W_out[idx];                   // already [i][k]
    if (tid < II) bout_s[tid] = b_out[tid];
    for (int idx = tid; idx < 2 * 4128; idx += NTHR)
        sm[idx] = 0.0f;                              // zero h_s, c_s
    __syncthreads();

    for (int t = 0; t < TT; t++) {
        // ---- load x tile for this timestep ----
        for (int idx = tid; idx < ROWS * II; idx += NTHR) {
            int row = idx / II, ii = idx % II;
            xs[idx] = x[(b0 + row) * (TT * II) + t * II + ii];
        }
        __syncthreads();   // xs ready; also orders prev-step h_s writes before GEMM reads

        // ---- gates = bias + x@Wih^T + h@Whh^T ----
        // acc pair jp = gate j (0..3) * 2 + p ; floats (n, n+1), n = j*128 + hu + 2p
        u64 acc[2][8];
        #pragma unroll
        for (int jp = 0; jp < 8; jp++) {
            int j = jp >> 1, p = jp & 1;
            u64 bv = *(const u64*)(bias_s + j * HH + hu + 2 * p);
            acc[0][jp] = bv;
            acc[1][jp] = bv;
        }
        // x projection (K = 17, all smem)
        #pragma unroll 1
        for (int ii = 0; ii < II; ii++) {
            u64 w[8];
            #pragma unroll
            for (int j = 0; j < 4; j++) {
                ulonglong2 wv = *(const ulonglong2*)(wih_s + ii * GG + j * HH + hu);
                w[2 * j] = wv.x; w[2 * j + 1] = wv.y;
            }
            u64 x0 = pack2(xs[(ty * 2 + 0) * II + ii]);
            u64 x1 = pack2(xs[(ty * 2 + 1) * II + ii]);
            #pragma unroll
            for (int jp = 0; jp < 8; jp++) {
                acc[0][jp] = fma2(x0, w[jp], acc[0][jp]);
                acc[1][jp] = fma2(x1, w[jp], acc[1][jp]);
            }
        }
        // recurrent GEMM (K = 128), W from L2 via transposed layout, prefetch k+1
        u64 wc[8];
        #pragma unroll
        for (int j = 0; j < 4; j++) {
            ulonglong2 wv = *(const ulonglong2*)(g_WtHH + 0 * GG + j * HH + hu);
            wc[2 * j] = wv.x; wc[2 * j + 1] = wv.y;
        }
        #pragma unroll 2
        for (int k = 0; k < HH - 1; k++) {
            u64 wn[8];
            #pragma unroll
            for (int j = 0; j < 4; j++) {
                ulonglong2 wv = *(const ulonglong2*)(g_WtHH + (k + 1) * GG + j * HH + hu);
                wn[2 * j] = wv.x; wn[2 * j + 1] = wv.y;
            }
            u64 h0 = pack2(h_s[(ty * 2 + 0) * 129 + k]);
            u64 h1 = pack2(h_s[(ty * 2 + 1) * 129 + k]);
            #pragma unroll
            for (int jp = 0; jp < 8; jp++) {
                acc[0][jp] = fma2(h0, wc[jp], acc[0][jp]);
                acc[1][jp] = fma2(h1, wc[jp], acc[1][jp]);
            }
            #pragma unroll
            for (int jp = 0; jp < 8; jp++) wc[jp] = wn[jp];
        }
        {   // epilogue k = 127
            u64 h0 = pack2(h_s[(ty * 2 + 0) * 129 + 127]);
            u64 h1 = pack2(h_s[(ty * 2 + 1) * 129 + 127]);
            #pragma unroll
            for (int jp = 0; jp < 8; jp++) {
                acc[0][jp] = fma2(h0, wc[jp], acc[0][jp]);
                acc[1][jp] = fma2(h1, wc[jp], acc[1][jp]);
            }
        }
        __syncthreads();   // all h_s reads done before elementwise writes

        // ---- elementwise LSTM cell update (this thread exclusively owns
        //      rows ty*2..ty*2+1, hidden units hu..hu+3) ----
        #pragma unroll
        for (int r = 0; r < 2; r++) {
            int m = ty * 2 + r;
            float gv[4][4];
            #pragma unroll
            for (int jp = 0; jp < 8; jp++) {
                int j = jp >> 1, p = jp & 1;
                unpack2(acc[r][jp], gv[j][2 * p], gv[j][2 * p + 1]);
            }
            #pragma unroll
            for (int e = 0; e < 4; e++) {
                float ig = sigf(gv[0][e]);
                float fg = sigf(gv[1][e]);
                float gg = tanh_fast(gv[2][e]);
                float og = sigf(gv[3][e]);
                float c  = fg * c_s[m * 129 + hu + e] + ig * gg;
                c_s[m * 129 + hu + e] = c;
                h_s[m * 129 + hu + e] = og * tanh_fast(c);
            }
        }
        __syncthreads();   // h_s updated before y GEMM reads

        // ---- y = h @ W_out^T + b_out ----
        for (int idx = tid; idx < ROWS * II; idx += NTHR) {
            int i = idx >> 5, row = idx & 31;   // 17*32 = 544, warp shares i (wout broadcast)
            float a = bout_s[i];
            const float* hp = h_s + row * 129;
            const float* wp = wout_s + i * HH;
            #pragma unroll 4
            for (int k = 0; k < HH; k++) a += hp[k] * wp[k];
            ys[i * 33 + row] = a;
        }
        __syncthreads();
        // coalesced writeout (rows contiguous in gmem)
        for (int idx = tid; idx < ROWS * II; idx += NTHR) {
            int row = idx / II, i = idx % II;
            out[(b0 + row) * (TT * II) + t * II + i] = ys[i * 33 + row];
        }
        // next-iteration __syncthreads (after xs load) orders ys reuse
    }
}

extern "C" void kernel_launch(void* const* d_in, const int* in_sizes, int n_in,
                              void* d_out, int out_size) {
    const float* x     = (const float*)d_in[0];
    const float* W_ih  = (const float*)d_in[1];
    const float* W_hh  = (const float*)d_in[2];
    const float* b_ih  = (const float*)d_in[3];
    const float* b_hh  = (const float*)d_in[4];
    const float* W_out = (const float*)d_in[5];
    const float* b_out = (const float*)d_in[6];
    float* out = (float*)d_out;

    // One-time transpose of W_hh (idempotent, cheap; re-run every call for determinism)
    whh_transpose_kernel<<<(HH * GG + 255) / 256, 256>>>(W_hh);

    cudaFuncSetAttribute(flow_lstm_kernel,
                         cudaFuncAttributeMaxDynamicSharedMemorySize, SMEM_BYTES);
    flow_lstm_kernel<<<BBATCH / ROWS, NTHR, SMEM_BYTES>>>(
        x, W_ih, b_ih, b_hh, W_out, b_out, out);
}

// round 6
// speedup vs baseline: 1.6076x; 1.6076x over previous
#include <cuda_runtime.h>

// Problem constants
#define II 17
#define HH 128
#define TT 19
#define BBATCH 32768
#define GG 512            // 4*H gate width
#define ROWS 32           // batch rows per CTA
#define NTHR 256          // 8 warps; each thread: 4 rows x 16 gate-cols
#define HP  132           // h/c row pitch (floats): mult of 4, !=0 mod strides

typedef unsigned long long u64;

// Transposed W_hh: [k=0..127][n=0..511], 256 KB, L2-resident.
__device__ __align__(16) float g_WtHH[HH * GG];

__device__ __forceinline__ u64 fma2(u64 a, u64 b, u64 c) {
    u64 d;
    asm("fma.rn.f32x2 %0, %1, %2, %3;" : "=l"(d) : "l"(a), "l"(b), "l"(c));
    return d;
}
__device__ __forceinline__ u64 pack2(float v) {
    u64 d;
    asm("mov.b64 %0, {%1, %1};" : "=l"(d) : "f"(v));
    return d;
}
__device__ __forceinline__ void unpack2(u64 a, float& lo, float& hi) {
    asm("mov.b64 {%0, %1}, %2;" : "=f"(lo), "=f"(hi) : "l"(a));
}
__device__ __forceinline__ float sigf(float x) {
    return 1.0f / (1.0f + __expf(-x));
}
__device__ __forceinline__ float tanh_fast(float x) {
    return 2.0f / (1.0f + __expf(-2.0f * x)) - 1.0f;
}

// One-time (idempotent) transpose of W_hh [512,128] -> g_WtHH [128,512]
__global__ void whh_transpose_kernel(const float* __restrict__ W_hh) {
    int idx = blockIdx.x * blockDim.x + threadIdx.x;
    if (idx < HH * GG) {
        int n = idx / HH;
        int k = idx % HH;
        g_WtHH[k * GG + n] = W_hh[idx];
    }
}

// SMEM float offsets
#define OFF_H     0                         // h  [32][132]
#define OFF_C     (OFF_H + ROWS * HP)       // c  [32][132]
#define OFF_WIH   (OFF_C + ROWS * HP)       // Wih^T [17][512]
#define OFF_WOUT  (OFF_WIH + II * GG)       // Wout  [17][128]
#define OFF_BIAS  (OFF_WOUT + II * HH)      // b_ih + b_hh [512]
#define OFF_BOUT  (OFF_BIAS + GG)           // b_out [17] (pad 32)
#define OFF_XS    (OFF_BOUT + 32)           // x tile [32][17]
#define OFF_YS    (OFF_XS + ROWS * II)      // y tile [17][33]
#define SMEM_FLOATS (OFF_YS + II * 33 + 16)
#define SMEM_BYTES  (SMEM_FLOATS * 4)

__global__ void __launch_bounds__(NTHR, 2)
flow_lstm_kernel(const float* __restrict__ x,
                 const float* __restrict__ W_ih,
                 const float* __restrict__ b_ih,
                 const float* __restrict__ b_hh,
                 const float* __restrict__ W_out,
                 const float* __restrict__ b_out,
                 float* __restrict__ out) {
    extern __shared__ float sm[];
    float* h_s    = sm + OFF_H;
    float* c_s    = sm + OFF_C;
    float* wih_s  = sm + OFF_WIH;   // [ii][n] transposed
    float* wout_s = sm + OFF_WOUT;  // [i][k]
    float* bias_s = sm + OFF_BIAS;
    float* bout_s = sm + OFF_BOUT;
    float* xs     = sm + OFF_XS;    // [32][17]
    float* ys     = sm + OFF_YS;    // [17][33]

    const int tid = threadIdx.x;
    const int tx  = tid & 31;       // gate-col group: hu = tx*4
    const int ty  = tid >> 5;       // warp 0..7 : rows m = ty*4 + r
    const int b0  = blockIdx.x * ROWS;
    const int hu  = tx * 4;
    const int m0  = ty * 4;

    // ---- one-time per-CTA setup ----
    for (int idx = tid; idx < GG * II; idx += NTHR) {
        int n = idx / II, i = idx % II;
        wih_s[i * GG + n] = W_ih[idx];              // transpose into smem
    }
    for (int idx = tid; idx < GG; idx += NTHR)
        bias_s[idx] = b_ih[idx] + b_hh[idx];
    for (int idx = tid; idx < II * HH; idx += NTHR)
        wout_s[idx] = W_out[idx];
    if (tid < II) bout_s[tid] = b_out[tid];
    for (int idx = tid; idx < 2 * ROWS * HP; idx += NTHR)
        sm[idx] = 0.0f;                              // zero h_s, c_s
    __syncthreads();

    for (int t = 0; t < TT; t++) {
        // ---- load x tile ----
        for (int idx = tid; idx < ROWS * II; idx += NTHR) {
            int row = idx / II, ii = idx % II;
            xs[idx] = x[(b0 + row) * (TT * II) + t * II + ii];
        }
        __syncthreads();

        // ---- gates = bias + x@Wih^T + h@Whh^T ----
        // acc[r][jp]: row m0+r, gate j=jp>>1, pair p=jp&1, cols n=j*128+hu+2p..+1
        u64 acc[4][8];
        #pragma unroll
        for (int jp = 0; jp < 8; jp++) {
            int j = jp >> 1, p = jp & 1;
            u64 bv = *(const u64*)(bias_s + j * HH + hu + 2 * p);
            #pragma unroll
            for (int r = 0; r < 4; r++) acc[r][jp] = bv;
        }

        // x projection (K=17, smem weights)
        #pragma unroll 1
        for (int ii = 0; ii < II; ii++) {
            u64 w[8];
            #pragma unroll
            for (int j = 0; j < 4; j++) {
                ulonglong2 wv = *(const ulonglong2*)(wih_s + ii * GG + j * HH + hu);
                w[2 * j] = wv.x; w[2 * j + 1] = wv.y;
            }
            u64 xv[4];
            #pragma unroll
            for (int r = 0; r < 4; r++) xv[r] = pack2(xs[(m0 + r) * II + ii]);
            #pragma unroll
            for (int r = 0; r < 4; r++)
                #pragma unroll
                for (int jp = 0; jp < 8; jp++)
                    acc[r][jp] = fma2(xv[r], w[jp], acc[r][jp]);
        }

        // recurrent GEMM (K=128), transposed weights streamed from L2/L1
        #pragma unroll 1
        for (int k = 0; k < HH; k += 2) {
            u64 wa[8], wb[8];
            #pragma unroll
            for (int j = 0; j < 4; j++) {
                ulonglong2 wv = *(const ulonglong2*)(g_WtHH + k * GG + j * HH + hu);
                wa[2 * j] = wv.x; wa[2 * j + 1] = wv.y;
            }
            #pragma unroll
            for (int j = 0; j < 4; j++) {
                ulonglong2 wv = *(const ulonglong2*)(g_WtHH + (k + 1) * GG + j * HH + hu);
                wb[2 * j] = wv.x; wb[2 * j + 1] = wv.y;
            }
            u64 ha[4], hb[4];
            #pragma unroll
            for (int r = 0; r < 4; r++) {
                float2 hv = *(const float2*)(h_s + (m0 + r) * HP + k);
                ha[r] = pack2(hv.x); hb[r] = pack2(hv.y);
            }
            #pragma unroll
            for (int r = 0; r < 4; r++)
                #pragma unroll
                for (int jp = 0; jp < 8; jp++)
                    acc[r][jp] = fma2(ha[r], wa[jp], acc[r][jp]);
            #pragma unroll
            for (int r = 0; r < 4; r++)
                #pragma unroll
                for (int jp = 0; jp < 8; jp++)
                    acc[r][jp] = fma2(hb[r], wb[jp], acc[r][jp]);
        }
        __syncthreads();   // all h_s reads done before elementwise writes

        // ---- elementwise LSTM cell (thread owns rows m0..m0+3, cols hu..hu+3) ----
        #pragma unroll
        for (int r = 0; r < 4; r++) {
            int m = m0 + r;
            float gv[4][4];
            #pragma unroll
            for (int jp = 0; jp < 8; jp++) {
                int j = jp >> 1, p = jp & 1;
                unpack2(acc[r][jp], gv[j][2 * p], gv[j][2 * p + 1]);
            }
            float4 c4 = *(float4*)(c_s + m * HP + hu);
            float cv[4] = {c4.x, c4.y, c4.z, c4.w};
            float hn[4];
            #pragma unroll
            for (int e = 0; e < 4; e++) {
                float ig = sigf(gv[0][e]);
                float fg = sigf(gv[1][e]);
                float gg = tanh_fast(gv[2][e]);
                float og = sigf(gv[3][e]);
                float c  = fg * cv[e] + ig * gg;
                cv[e] = c;
                hn[e] = og * tanh_fast(c);
            }
            *(float4*)(c_s + m * HP + hu) = make_float4(cv[0], cv[1], cv[2], cv[3]);
            *(float4*)(h_s + m * HP + hu) = make_float4(hn[0], hn[1], hn[2], hn[3]);
        }
        __syncthreads();   // h_s updated before y GEMM reads

        // ---- y = h @ W_out^T + b_out (float4 dot, w broadcast per warp) ----
        for (int idx = tid; idx < ROWS * II; idx += NTHR) {
            int i = idx >> 5, row = idx & 31;    // 544 tasks, warp shares i
            float a = bout_s[i];
            const float4* h4 = (const float4*)(h_s + row * HP);
            const float4* w4 = (const float4*)(wout_s + i * HH);
            #pragma unroll 8
            for (int k4 = 0; k4 < HH / 4; k4++) {
                float4 hv = h4[k4], wv = w4[k4];
                a += hv.x * wv.x + hv.y * wv.y + hv.z * wv.z + hv.w * wv.w;
            }
            ys[i * 33 + row] = a;
        }
        __syncthreads();
        // coalesced writeout
        for (int idx = tid; idx < ROWS * II; idx += NTHR) {
            int row = idx / II, i = idx % II;
            out[(b0 + row) * (TT * II) + t * II + i] = ys[i * 33 + row];
        }
        // next-iteration __syncthreads (after xs load) orders ys reuse
    }
}

extern "C" void kernel_launch(void* const* d_in, const int* in_sizes, int n_in,
                              void* d_out, int out_size) {
    const float* x     = (const float*)d_in[0];
    const float* W_ih  = (const float*)d_in[1];
    const float* W_hh  = (const float*)d_in[2];
    const float* b_ih  = (const float*)d_in[3];
    const float* b_hh  = (const float*)d_in[4];
    const float* W_out = (const float*)d_in[5];
    const float* b_out = (const float*)d_in[6];
    float* out = (float*)d_out;

    whh_transpose_kernel<<<(HH * GG + 255) / 256, 256>>>(W_hh);

    cudaFuncSetAttribute(flow_lstm_kernel,
                         cudaFuncAttributeMaxDynamicSharedMemorySize, SMEM_BYTES);
    flow_lstm_kernel<<<BBATCH / ROWS, NTHR, SMEM_BYTES>>>(
        x, W_ih, b_ih, b_hh, W_out, b_out, out);
}

// round 17
// speedup vs baseline: 3.8886x; 2.4189x over previous
#include <cuda_runtime.h>
#include <cuda_fp16.h>
#include <cstdint>

#define II 17
#define HH 128
#define TT 19
#define NTHR 256
#define NCTA 256
#define KP 168                 // padded K pitch in halfs
#define PB (KP*2)              // 336-byte row pitch
#define WROWS 544              // 512 gate rows (permuted) + 32 W_out rows
#define SA_OFF 0
#define SA_BYTES (128*PB)      // 43008
#define SW_OFF SA_BYTES
#define SW_BYTES (WROWS*PB)    // 182784
#define SMEM_TOTAL (SW_OFF + SW_BYTES)   // 225792 <= 227KB opt-in

// Pre-packed fp16 weight image (built once per launch by pack_w)
__device__ __align__(16) __half gWpack[WROWS*KP];

// Row permutation: gate row n = j*128+u  ->  pn s.t. chunk/warp tiles hold all
// 4 gates of each unit. Decode (fill side): pn -> c=pn>>7, r7=pn&127,
// q=r7>>5, j=(r7>>3)&3, u8=r7&7, u = 32c+8q+u8.
__global__ void pack_w(const float* __restrict__ W_ih, const float* __restrict__ W_hh,
                       const float* __restrict__ b_ih, const float* __restrict__ b_hh,
                       const float* __restrict__ W_out){
    int idx = blockIdx.x*256 + threadIdx.x;
    if (idx >= WROWS*KP) return;
    int row = idx / KP, k = idx - row*KP;
    float v = 0.0f;
    if (row < 512){
        int c = row>>7, r7 = row&127, q = r7>>5, j = (r7>>3)&3, u8 = r7&7;
        int n = j*128 + 32*c + 8*q + u8;
        if (k < II)                  v = W_ih[n*II + k];
        else if (k == II)            v = b_ih[n] + b_hh[n];
        else if (k >= 32 && k < 160) v = W_hh[n*HH + (k-32)];
    } else {
        int np = row - 512;
        if (np < II && k >= 32 && k < 160) v = W_out[np*HH + (k-32)];
    }
    gWpack[row*KP + k] = __float2half_rn(v);
}

__device__ __forceinline__ uint32_t smem_u32(const void* p){
    uint32_t a; asm("{ .reg .u64 t; cvta.to.shared.u64 t, %1; cvt.u32.u64 %0, t; }":"=r"(a):"l"(p)); return a;
}
__device__ __forceinline__ void ldmx4(uint32_t* r, uint32_t a){
    asm volatile("ldmatrix.sync.aligned.m8n8.x4.shared.b16 {%0,%1,%2,%3}, [%4];"
        : "=r"(r[0]),"=r"(r[1]),"=r"(r[2]),"=r"(r[3]) : "r"(a));
}
__device__ __forceinline__ void ldmx2(uint32_t* r, uint32_t a){
    asm volatile("ldmatrix.sync.aligned.m8n8.x2.shared.b16 {%0,%1}, [%2];"
        : "=r"(r[0]),"=r"(r[1]) : "r"(a));
}
__device__ __forceinline__ void mma16816(float* d, const uint32_t* a, const uint32_t* b){
    asm volatile("mma.sync.aligned.m16n8k16.row.col.f32.f16.f16.f32 "
        "{%0,%1,%2,%3}, {%4,%5,%6,%7}, {%8,%9}, {%0,%1,%2,%3};"
        : "+f"(d[0]),"+f"(d[1]),"+f"(d[2]),"+f"(d[3])
        : "r"(a[0]),"r"(a[1]),"r"(a[2]),"r"(a[3]),"r"(b[0]),"r"(b[1]));
}
__device__ __forceinline__ float sigf(float v){ return 1.0f/(1.0f+__expf(-v)); }
__device__ __forceinline__ float tanhe(float v){ return 2.0f/(1.0f+__expf(-2.0f*v)) - 1.0f; }

__global__ void __launch_bounds__(NTHR,1)
lstm_mma(const float* __restrict__ x, const float* __restrict__ b_out,
         float* __restrict__ out)
{
    extern __shared__ __align__(16) char smc[];
    const uint32_t sb = smem_u32(smc);
    const int tid = threadIdx.x, w = tid>>5, lane = tid&31;
    const int mg = w&3, ng = w>>2;           // gate-phase warp tile: rows 32mg, chunk-cols 64ng
    const int b0 = blockIdx.x*128;
    const int laneq = lane>>2, lanep = lane&3, lane7 = lane&7;

    // ---- init: zero A tile, copy packed W, ones column, x_0 ----
    for (int i=tid; i<SA_BYTES/4; i+=NTHR) ((uint32_t*)smc)[i] = 0u;
    { const uint4* src = (const uint4*)gWpack;
      uint4* dst = (uint4*)(smc + SW_OFF);
      for (int i=tid; i<SW_BYTES/16; i+=NTHR) dst[i] = src[i]; }
    __syncthreads();
    if (tid < 128) *(__half*)(smc + tid*PB + 2*II) = __float2half_rn(1.0f);
    for (int i=tid; i<128*II; i+=NTHR){ int r=i/II, cc=i-r*II;
        *(__half*)(smc + r*PB + cc*2) = __float2half_rn(x[(size_t)(b0+r)*(TT*II) + cc]); }
    float bo[6];
    #pragma unroll
    for (int nt2=0; nt2<3; nt2++)
        #pragma unroll
        for (int e=0; e<2; e++){ int col = 8*nt2 + 2*lanep + e;
            bo[nt2*2+e] = (col<II) ? b_out[col] : 0.0f; }
    __syncthreads();

    // ldmatrix per-lane address bases
    const uint32_t aAbase = sb + SA_OFF
        + (uint32_t)((32*mg + ((lane>>3)&1)*8 + lane7)*PB) + (uint32_t)((lane>>4)*16);
    const uint32_t bBlane = (uint32_t)((((lane>>4)*8) + lane7)*PB) + (uint32_t)(((lane>>3)&1)*16);
    const uint32_t aYbase = sb + SA_OFF
        + (uint32_t)((16*w + ((lane>>3)&1)*8 + lane7)*PB) + (uint32_t)((lane>>4)*16);
    const uint32_t bY01   = sb + SW_OFF
        + (uint32_t)((512 + (lane>>4)*8 + lane7)*PB) + (uint32_t)(((lane>>3)&1)*16);
    const uint32_t bY2    = sb + SW_OFF
        + (uint32_t)((528 + lane7)*PB) + (uint32_t)(((lane>>3)&1)*16);

    float    creg[64];     // c state: [(c*2+m)*2+qh]*4+d
    uint32_t hreg[32];     // new-h half2: [(c*2+m)*2+qh]*2+rh
    #pragma unroll
    for (int i=0;i<64;i++) creg[i]=0.0f;

    for (int t=0; t<TT; t++){
        // ===== gate phase: D[128,512] = [x|1|h] @ Wcat^T, chunked 4x128 =====
        #pragma unroll 1
        for (int c=0; c<4; c++){
            float acc[2][8][4];
            #pragma unroll
            for (int m=0;m<2;m++)
                #pragma unroll
                for (int n=0;n<8;n++)
                    #pragma unroll
                    for (int d=0;d<4;d++) acc[m][n][d]=0.0f;
            const uint32_t bBbase = sb + SW_OFF + (uint32_t)((128*c + 64*ng)*PB) + bBlane;
            #pragma unroll
            for (int ks=0; ks<10; ks++){
                uint32_t a0[4], a1[4];
                ldmx4(a0, aAbase + ks*32);
                ldmx4(a1, aAbase + 16*PB + ks*32);
                #pragma unroll
                for (int np=0; np<4; np++){
                    uint32_t bb[4];
                    ldmx4(bb, bBbase + np*16*PB + ks*32);
                    mma16816(acc[0][np*2],   a0, bb);
                    mma16816(acc[0][np*2+1], a0, bb+2);
                    mma16816(acc[1][np*2],   a1, bb);
                    mma16816(acc[1][np*2+1], a1, bb+2);
                }
            }
            // activations: acc[m][qh*4+j][d], j = gate (i,f,g,o)
            #pragma unroll
            for (int m=0;m<2;m++)
                #pragma unroll
                for (int qh=0;qh<2;qh++)
                    #pragma unroll
                    for (int rh=0;rh<2;rh++){
                        float hv0, hv1;
                        {
                            int d = 2*rh;
                            float iv=sigf(acc[m][qh*4+0][d]), fv=sigf(acc[m][qh*4+1][d]);
                            float gv=tanhe(acc[m][qh*4+2][d]), ov=sigf(acc[m][qh*4+3][d]);
                            int ci = ((c*2+m)*2+qh)*4+d;
                            float cc2 = fv*creg[ci] + iv*gv; creg[ci]=cc2;
                            hv0 = ov*tanhe(cc2);
                        }
                        {
                            int d = 2*rh+1;
                            float iv=sigf(acc[m][qh*4+0][d]), fv=sigf(acc[m][qh*4+1][d]);
                            float gv=tanhe(acc[m][qh*4+2][d]), ov=sigf(acc[m][qh*4+3][d]);
                            int ci = ((c*2+m)*2+qh)*4+d;
                            float cc2 = fv*creg[ci] + iv*gv; creg[ci]=cc2;
                            hv1 = ov*tanhe(cc2);
                        }
                        __half2 p = __floats2half2_rn(hv0, hv1);
                        hreg[((c*2+m)*2+qh)*2+rh] = *(uint32_t*)&p;
                    }
        }
        __syncthreads();     // all warps done reading old h/x

        // ===== store new h; stage x_{t+1} =====
        #pragma unroll
        for (int c=0;c<4;c++)
            #pragma unroll
            for (int m=0;m<2;m++)
                #pragma unroll
                for (int qh=0;qh<2;qh++)
                    #pragma unroll
                    for (int rh=0;rh<2;rh++){
                        int row  = 32*mg + 16*m + 8*rh + laneq;
                        int colb = (32 + 32*c + 16*ng + 8*qh + 2*lanep)*2;
                        *(uint32_t*)(smc + row*PB + colb) = hreg[((c*2+m)*2+qh)*2+rh];
                    }
        if (t+1 < TT){
            for (int i=tid; i<128*II; i+=NTHR){ int r=i/II, cc=i-r*II;
                *(__half*)(smc + r*PB + cc*2) =
                    __float2half_rn(x[(size_t)(b0+r)*(TT*II) + (t+1)*II + cc]); }
        }
        __syncthreads();     // new h visible

        // ===== y phase: y[128,17] = h @ W_out^T + b_out (k = 32..159) =====
        {
            float ay[3][4];
            #pragma unroll
            for (int n=0;n<3;n++)
                #pragma unroll
                for (int d=0;d<4;d++) ay[n][d]=0.0f;
            #pragma unroll
            for (int ks=2; ks<10; ks++){
                uint32_t a[4], b01[4], b2[2];
                ldmx4(a,   aYbase + ks*32);
                ldmx4(b01, bY01   + ks*32);
                ldmx2(b2,  bY2    + ks*32);
                mma16816(ay[0], a, b01);
                mma16816(ay[1], a, b01+2);
                mma16816(ay[2], a, b2);
            }
            #pragma unroll
            for (int nt2=0; nt2<3; nt2++)
                #pragma unroll
                for (int d=0; d<4; d++){
                    int col = 8*nt2 + 2*lanep + (d&1);
                    if (col < II){
                        int row = 16*w + 8*(d>>1) + laneq;
                        out[(size_t)(b0+row)*(TT*II) + t*II + col] = ay[nt2][d] + bo[nt2*2+(d&1)];
                    }
                }
        }
        __syncthreads();     // y reads done before next-step h overwrite
    }
}

extern "C" void kernel_launch(void* const* d_in, const int* in_sizes, int n_in,
                              void* d_out, int out_size) {
    const float* x     = (const float*)d_in[0];
    const float* W_ih  = (const float*)d_in[1];
    const float* W_hh  = (const float*)d_in[2];
    const float* b_ih  = (const float*)d_in[3];
    const float* b_hh  = (const float*)d_in[4];
    const float* W_out = (const float*)d_in[5];
    const float* b_out = (const float*)d_in[6];
    float* out = (float*)d_out;

    pack_w<<<(WROWS*KP + 255)/256, 256>>>(W_ih, W_hh, b_ih, b_hh, W_out);

    cudaFuncSetAttribute(lstm_mma, cudaFuncAttributeMaxDynamicSharedMemorySize, SMEM_TOTAL);
    lstm_mma<<<NCTA, NTHR, SMEM_TOTAL>>>(x, b_out, out);
}